// round 8
// baseline (speedup 1.0000x reference)
#include <cuda_runtime.h>

// Problem constants
#define B_TOT 2048
#define T_LEN 128
#define DIN   64
#define UDIM  128
#define NG    512   // 4*U
#define KTOT  192   // DIN + U
#define BT    8     // batch rows per CTA (small tile -> 4 CTAs/SM)
#define NTH   256   // each thread: 2 adjacent gate columns x all 8 batch rows
#define XH_S  12    // row stride for [x|h] tile (floats): 8 + pad, 48B (16B-aligned)
#define GS_S  12    // row stride for gate staging (floats)
#define KUF   4     // weight prefetch block

// Pre-transposed fused weights: g_Wt[k][n], k in [0,192): k<64 -> W_ih, else W_hh
__device__ float g_Wt[KTOT * NG];
__device__ float g_bias[NG];

__global__ void prep_kernel(const float* __restrict__ W_ih, const float* __restrict__ W_hh,
                            const float* __restrict__ b_ih, const float* __restrict__ b_hh) {
    int k = blockIdx.x;
    int n = threadIdx.x;
    g_Wt[k * NG + n] = (k < DIN) ? W_ih[n * DIN + k] : W_hh[n * UDIM + (k - DIN)];
    if (k == 0) g_bias[n] = b_ih[n] + b_hh[n];
}

__device__ __forceinline__ float fsig(float x) {
    return 1.0f / (1.0f + __expf(-x));
}
__device__ __forceinline__ float ftanh(float x) {
    float a = fabsf(x);
    float e = __expf(2.0f * a);
    float r = 1.0f - 2.0f / (1.0f + e);
    return copysignf(r, x);
}

// packed fp32x2 FMA (sm_100a): d = a*b + d  (same fp32 RN rounding as FFMA)
#define FFMA2(d, a, b) \
    asm("fma.rn.f32x2 %0, %1, %2, %0;" : "+l"(d) : "l"(a), "l"(b))

__device__ __forceinline__ unsigned long long splat2(float w) {
    unsigned long long r;
    asm("mov.b64 %0, {%1, %1};" : "=l"(r) : "f"(w));
    return r;
}
__device__ __forceinline__ void unpack2(unsigned long long p, float& lo, float& hi) {
    asm("mov.b64 {%0, %1}, %2;" : "=f"(lo), "=f"(hi) : "l"(p));
}

__global__ void __launch_bounds__(NTH, 4)
lstm_kernel(const float* __restrict__ x_st, const float* __restrict__ x_sc,
            const float* __restrict__ bn_gamma, const float* __restrict__ bn_beta,
            const float* __restrict__ bn_mean, const float* __restrict__ bn_var,
            float* __restrict__ out) {
    // sm_xh: [192][XH_S]  rows 0..63 = x_t (transposed, [k][b]), rows 64..191 = h ([u][b])
    // sm_gs: [512][GS_S]  activated gates, [n][b]
    __shared__ float sm_xh[KTOT * XH_S];   // 9.2 KB
    __shared__ float sm_gs[NG * GS_S];     // 24.6 KB  (total 33.8 KB, 4 CTAs = 135 KB/SM)

    const int path  = blockIdx.y;            // 0 = SNN (st), 1 = ANN (sc)
    const int bbase = blockIdx.x * BT;
    const float* __restrict__ xin = (path == 0) ? x_st : x_sc;
    const float* __restrict__ xrow = xin + (size_t)bbase * T_LEN * DIN;

    const int i    = threadIdx.x;            // owns gate columns n0=2i, n0+1 (all 8 rows)
    const int n0   = 2 * i;
    const int gate = n0 >> 7;                // 0:i 1:f 2:g 3:o (both cols same gate)
    // state mapping: thread owns (u, 4 batch rows)
    const int u    = i & (UDIM - 1);
    const int sb0  = (i >> 7) * 4;           // rows sb0..sb0+3

    // x staging: 512 elements (8 rows x 64 cols), 2 per thread
    const int xb0 = i >> 6,           xk0 = i & 63;          // element i
    const int xb1 = (i + NTH) >> 6;                          // element i+256 (same k-col)

    // zero the whole [x|h] tile (h starts at 0, pads stay 0)
    for (int idx = i; idx < KTOT * XH_S; idx += NTH) sm_xh[idx] = 0.0f;

    float c[4], m[4], s[4];
#pragma unroll
    for (int j = 0; j < 4; j++) { c[j] = 0.0f; m[j] = 0.0f; s[j] = 0.0f; }

    const unsigned long long biasp0 = splat2(g_bias[n0]);
    const unsigned long long biasp1 = splat2(g_bias[n0 + 1]);
    const float2* __restrict__ Wp = (const float2*)(g_Wt + n0);  // stride NG/2 float2 per k

    // preload x_0 and stage it (pre-barrier, so no race)
    float rx0 = xrow[((size_t)xb0 * T_LEN + 0) * DIN + xk0];
    float rx1 = xrow[((size_t)xb1 * T_LEN + 0) * DIN + xk0];
    sm_xh[xk0 * XH_S + xb0] = rx0;
    sm_xh[xk0 * XH_S + xb1] = rx1;

    for (int t = 0; t < T_LEN; t++) {
        __syncthreads();   // (A) x_t and h_t visible to everyone

        // issue next step's x loads early; consumed after barrier (B)
        if (t + 1 < T_LEN) {
            rx0 = xrow[((size_t)xb0 * T_LEN + (t + 1)) * DIN + xk0];
            rx1 = xrow[((size_t)xb1 * T_LEN + (t + 1)) * DIN + xk0];
        }

        // ---- gates[b][n] = sum_k xh[k][b] * Wt[k][n] + bias; 2 cols x 8 rows ----
        unsigned long long a0[4], a1[4];
#pragma unroll
        for (int j = 0; j < 4; j++) { a0[j] = biasp0; a1[j] = biasp1; }

        float2 w[KUF], wn[KUF];
#pragma unroll
        for (int q = 0; q < KUF; q++) w[q] = __ldg(Wp + q * (NG / 2));

        for (int kb = 0; kb < KTOT; kb += KUF) {
            if (kb + KUF < KTOT) {
#pragma unroll
                for (int q = 0; q < KUF; q++) wn[q] = __ldg(Wp + (kb + KUF + q) * (NG / 2));
            }
#pragma unroll
            for (int q = 0; q < KUF; q++) {
                unsigned long long w0 = splat2(w[q].x);
                unsigned long long w1 = splat2(w[q].y);
                const ulonglong2* xr = (const ulonglong2*)(sm_xh + (kb + q) * XH_S);
                ulonglong2 p0 = xr[0];   // batch pairs (0,1),(2,3)  -- broadcast
                ulonglong2 p1 = xr[1];   // (4,5),(6,7)
                FFMA2(a0[0], p0.x, w0);  FFMA2(a1[0], p0.x, w1);
                FFMA2(a0[1], p0.y, w0);  FFMA2(a1[1], p0.y, w1);
                FFMA2(a0[2], p1.x, w0);  FFMA2(a1[2], p1.x, w1);
                FFMA2(a0[3], p1.y, w0);  FFMA2(a1[3], p1.y, w1);
            }
#pragma unroll
            for (int q = 0; q < KUF; q++) w[q] = wn[q];
        }

        // ---- activations, stage to smem ----
        float v0[8], v1[8];
#pragma unroll
        for (int j = 0; j < 4; j++) {
            unpack2(a0[j], v0[2 * j], v0[2 * j + 1]);
            unpack2(a1[j], v1[2 * j], v1[2 * j + 1]);
        }
        if (gate == 2) {
#pragma unroll
            for (int j = 0; j < 8; j++) { v0[j] = ftanh(v0[j]); v1[j] = ftanh(v1[j]); }
        } else {
#pragma unroll
            for (int j = 0; j < 8; j++) { v0[j] = fsig(v0[j]); v1[j] = fsig(v1[j]); }
        }
        {
            float4* g0 = (float4*)(sm_gs + n0 * GS_S);
            g0[0] = make_float4(v0[0], v0[1], v0[2], v0[3]);
            g0[1] = make_float4(v0[4], v0[5], v0[6], v0[7]);
            float4* g1 = (float4*)(sm_gs + (n0 + 1) * GS_S);
            g1[0] = make_float4(v1[0], v1[1], v1[2], v1[3]);
            g1[1] = make_float4(v1[4], v1[5], v1[6], v1[7]);
        }
        __syncthreads();   // (B) all gates visible; all gemm reads of sm_xh done

        // ---- stage next x_t (safe now: gemm reads finished) ----
        if (t + 1 < T_LEN) {
            sm_xh[xk0 * XH_S + xb0] = rx0;
            sm_xh[xk0 * XH_S + xb1] = rx1;
        }

        // ---- state update: thread owns (u, rows sb0..sb0+3) ----
        float4 iv = *(const float4*)(sm_gs + (0 * UDIM + u) * GS_S + sb0);
        float4 fv = *(const float4*)(sm_gs + (1 * UDIM + u) * GS_S + sb0);
        float4 gv = *(const float4*)(sm_gs + (2 * UDIM + u) * GS_S + sb0);
        float4 ov = *(const float4*)(sm_gs + (3 * UDIM + u) * GS_S + sb0);
        float ia[4] = {iv.x, iv.y, iv.z, iv.w};
        float fa[4] = {fv.x, fv.y, fv.z, fv.w};
        float ga[4] = {gv.x, gv.y, gv.z, gv.w};
        float oa[4] = {ov.x, ov.y, ov.z, ov.w};
        float hv[4];
        if (path) {        // ANN: h = o * tanh(c)
#pragma unroll
            for (int j = 0; j < 4; j++) {
                c[j] = fa[j] * c[j] + ia[j] * ga[j];
                hv[j] = oa[j] * ftanh(c[j]);
                s[j] += hv[j];
            }
        } else {           // SNN: integrate-and-fire, spikes feed back as h
#pragma unroll
            for (int j = 0; j < 4; j++) {
                c[j] = fa[j] * c[j] + ia[j] * ga[j];
                m[j] += oa[j] * ftanh(c[j]);
                float spk = (m[j] >= 1.0f) ? 1.0f : 0.0f;
                m[j] -= spk;
                hv[j] = spk;
                s[j] += spk;
            }
        }
        *(float4*)(sm_xh + (DIN + u) * XH_S + sb0) = make_float4(hv[0], hv[1], hv[2], hv[3]);
        // next iteration's barrier (A) orders these writes before the next gemm
    }

    // ---- epilogue: temporal mean + BatchNorm (eval mode) ----
    float scale = bn_gamma[u] * rsqrtf(bn_var[u] + 1e-5f);
    float shift = bn_beta[u] - bn_mean[u] * scale;
    const float inv = 1.0f / (float)T_LEN;
    size_t ob = ((size_t)path * B_TOT + bbase + sb0) * UDIM + u;
#pragma unroll
    for (int j = 0; j < 4; j++) {
        out[ob + (size_t)j * UDIM] = s[j] * inv * scale + shift;
    }
}

extern "C" void kernel_launch(void* const* d_in, const int* in_sizes, int n_in,
                              void* d_out, int out_size) {
    const float* x_st  = (const float*)d_in[0];
    const float* x_sc  = (const float*)d_in[1];
    const float* W_ih  = (const float*)d_in[2];
    const float* W_hh  = (const float*)d_in[3];
    const float* b_ih  = (const float*)d_in[4];
    const float* b_hh  = (const float*)d_in[5];
    const float* gamma = (const float*)d_in[6];
    const float* beta  = (const float*)d_in[7];
    const float* mean  = (const float*)d_in[8];
    const float* var   = (const float*)d_in[9];

    prep_kernel<<<KTOT, NG>>>(W_ih, W_hh, b_ih, b_hh);

    dim3 grid(B_TOT / BT, 2);   // (256, 2) = 512 CTAs, 4 per SM
    lstm_kernel<<<grid, NTH>>>(x_st, x_sc, gamma, beta, mean, var, (float*)d_out);
}